// round 9
// baseline (speedup 1.0000x reference)
#include <cuda_runtime.h>
#include <cuda_bf16.h>
#include <cstdint>

#define T_STEPS 512
#define BATCH   512
#define INSZ    300
#define HID     16
#define NG      64
#define NROWS   (T_STEPS*BATCH)     // 262144
#define TILE_M  256
#define NTILES  (NROWS/TILE_M)      // 1024
#define GRID_G  148
#define STRIDE_T (BATCH*NG)
#define ASTRIDE 72                  // fp32 row stride in A smem (conflict-free for bf16 frags)

#define A_ELEMS (TILE_M*ASTRIDE)    // 18432 floats per buffer
#define B_WORDS (19*64*8)           // 9728 uint32 (bf16x2 pairs)
#define SMEM_BYTES (2*A_ELEMS*4 + B_WORDS*4)   // 186368

__device__ float d_xg[(size_t)(NROWS + 4 * BATCH) * NG];

// ---------------- asm helpers ----------------
__device__ __forceinline__ uint32_t smem_u32(const void* p) {
    uint32_t a;
    asm("{ .reg .u64 t; cvta.to.shared.u64 t, %1; cvt.u32.u64 %0, t; }" : "=r"(a) : "l"(p));
    return a;
}
__device__ __forceinline__ void cp16(uint32_t sa, const float* g) {
    asm volatile("cp.async.cg.shared.global [%0], [%1], 16;" :: "r"(sa), "l"(g) : "memory");
}
#define CP_COMMIT() asm volatile("cp.async.commit_group;" ::: "memory")
#define CP_WAIT1()  asm volatile("cp.async.wait_group 1;" ::: "memory")

__device__ __forceinline__ void mma16816(float* d, uint32_t a0, uint32_t a1, uint32_t a2,
                                         uint32_t a3, uint32_t b0, uint32_t b1) {
    asm volatile(
        "mma.sync.aligned.m16n8k16.row.col.f32.bf16.bf16.f32 "
        "{%0,%1,%2,%3}, {%4,%5,%6,%7}, {%8,%9}, {%0,%1,%2,%3};"
        : "+f"(d[0]), "+f"(d[1]), "+f"(d[2]), "+f"(d[3])
        : "r"(a0), "r"(a1), "r"(a2), "r"(a3), "r"(b0), "r"(b1));
}
__device__ __forceinline__ uint32_t packbf(float lo, float hi) {
    __nv_bfloat162 p = __floats2bfloat162_rn(lo, hi);
    return *reinterpret_cast<uint32_t*>(&p);
}

// copy one 64-col K-chunk of a 256-row tile (256 threads)
__device__ __forceinline__ void cp_chunk(const float* __restrict__ x, uint32_t abase,
                                         int tile, int ch) {
    const int tid = threadIdx.x;
    const int j  = tid & 15;
    const int rr = tid >> 4;
    const int c0 = ch * 64;
    const int jmax = (ch == 4) ? 11 : 16;
#pragma unroll
    for (int p = 0; p < 16; p++) {
        int r = p * 16 + rr;
        uint32_t soff = abase + ((uint32_t)(r * ASTRIDE) + 4u * (uint32_t)j) * 4u;
        if (j < jmax) {
            cp16(soff, x + (size_t)(tile * TILE_M + r) * INSZ + c0 + 4 * j);
        } else if (ch == 4 && j == 11) {
            asm volatile("st.shared.v4.u32 [%0], {%1,%1,%1,%1};" :: "r"(soff), "r"(0u) : "memory");
        }
    }
    CP_COMMIT();
}

// ---------------- GEMM: d_xg = x @ W_ih^T  (bf16 mma.sync m16n8k16, persistent) ----------------
__global__ void __launch_bounds__(256, 1)
gemm_kernel(const float* __restrict__ x, const float* __restrict__ W) {
    extern __shared__ float sm[];
    float* sA0 = sm;
    float* sA1 = sm + A_ELEMS;
    uint32_t* sB = reinterpret_cast<uint32_t*>(sm + 2 * A_ELEMS);
    const uint32_t sbase = smem_u32(sm);
    const uint32_t aB[2] = { sbase, sbase + A_ELEMS * 4u };
    float* sAp[2] = { sA0, sA1 };

    const int tid  = threadIdx.x;
    const int w    = tid >> 5;
    const int lane = tid & 31;
    const int g    = lane >> 2;
    const int tg   = lane & 3;

    cp_chunk(x, aB[0], blockIdx.x, 0);

    // B fill (once): W[n][k] fp32 -> bf16x2 fragment-pair layout
    for (int i = tid; i < 19 * 64 * 4; i += 256) {
        int s = i >> 8;
        int n = (i >> 2) & 63;
        int t = i & 3;
        int k0 = 16 * s + 2 * t;
        const float* Wn = W + (size_t)n * INSZ;
        float v0 = (k0     < INSZ) ? Wn[k0]     : 0.0f;
        float v1 = (k0 + 1 < INSZ) ? Wn[k0 + 1] : 0.0f;
        float v2 = (k0 + 8 < INSZ) ? Wn[k0 + 8] : 0.0f;
        float v3 = (k0 + 9 < INSZ) ? Wn[k0 + 9] : 0.0f;
        int base = ((s * 64 + n) * 4 + t) * 2;
        sB[base]     = packbf(v0, v1);
        sB[base + 1] = packbf(v2, v3);
    }
    __syncthreads();

    int buf = 0;
    for (int tile = blockIdx.x; tile < NTILES; tile += GRID_G) {
        float acc[2][8][4];
#pragma unroll
        for (int i = 0; i < 2; i++)
#pragma unroll
            for (int j = 0; j < 8; j++)
#pragma unroll
                for (int r = 0; r < 4; r++) acc[i][j][r] = 0.0f;

        for (int ch = 0; ch < 5; ch++) {
            int ntile = tile, nch = ch + 1;
            if (nch == 5) { ntile = tile + GRID_G; nch = 0; }
            if (ntile < NTILES) cp_chunk(x, aB[buf ^ 1], ntile, nch);
            else CP_COMMIT();
            CP_WAIT1();
            __syncthreads();

            const float* A = sAp[buf];
            const int nsl = (ch == 4) ? 3 : 4;
            for (int sl = 0; sl < nsl; sl++) {
                const int s = ch * 4 + sl;
                uint2 bb[8];
                const uint2* Bf = reinterpret_cast<const uint2*>(sB)
                                + ((s * 64 + g) * 4 + tg);
#pragma unroll
                for (int j = 0; j < 8; j++) bb[j] = Bf[j * 32];
#pragma unroll
                for (int i = 0; i < 2; i++) {
                    int r0 = w * 32 + i * 16 + g;
                    const float* Ab = A + r0 * ASTRIDE + sl * 16 + 2 * tg;
                    float2 f0 = *reinterpret_cast<const float2*>(Ab);
                    float2 f1 = *reinterpret_cast<const float2*>(Ab + 8 * ASTRIDE);
                    float2 f2 = *reinterpret_cast<const float2*>(Ab + 8);
                    float2 f3 = *reinterpret_cast<const float2*>(Ab + 8 * ASTRIDE + 8);
                    uint32_t a0 = packbf(f0.x, f0.y);
                    uint32_t a1 = packbf(f1.x, f1.y);
                    uint32_t a2 = packbf(f2.x, f2.y);
                    uint32_t a3 = packbf(f3.x, f3.y);
#pragma unroll
                    for (int j = 0; j < 8; j++)
                        mma16816(acc[i][j], a0, a1, a2, a3, bb[j].x, bb[j].y);
                }
            }
            __syncthreads();
            buf ^= 1;
        }

#pragma unroll
        for (int i = 0; i < 2; i++) {
            int r0 = tile * TILE_M + w * 32 + i * 16 + g;
#pragma unroll
            for (int j = 0; j < 8; j++) {
                int col = j * 8 + tg * 2;
                *reinterpret_cast<float2*>(&d_xg[(size_t)r0 * NG + col]) =
                    make_float2(acc[i][j][0], acc[i][j][1]);
                *reinterpret_cast<float2*>(&d_xg[(size_t)(r0 + 8) * NG + col]) =
                    make_float2(acc[i][j][2], acc[i][j][3]);
            }
        }
    }
}

// ---------------- scan: 2 batch elements per warp, 4 gates per lane ----------------
__device__ __forceinline__ float tanhapx(float x) {
    float y;
    asm("tanh.approx.f32 %0, %1;" : "=f"(y) : "f"(x));
    return y;
}
__device__ __forceinline__ float sigt(float x) {
    return fmaf(tanhapx(0.5f * x), 0.5f, 0.5f);
}
__device__ __forceinline__ float sigx(float x) {
    float e = __expf(-x);
    return __fdividef(1.0f, 1.0f + e);
}

__global__ void __launch_bounds__(64, 1)
scan_kernel(const float* __restrict__ Whh,
            const float* __restrict__ b_ih, const float* __restrict__ b_hh,
            const float* __restrict__ W1, const float* __restrict__ b1,
            const float* __restrict__ W2, const float* __restrict__ b2,
            float* __restrict__ out) {
    const int wgl  = blockIdx.x * 2 + (threadIdx.x >> 5);   // 0..255
    const int lane = threadIdx.x & 31;
    const int l    = lane & 15;         // hidden unit owned by this lane
    const int side = lane >> 4;         // 0: element A, 1: element B
    const int b    = wgl + side * 256;  // batch element
    const unsigned FULL = 0xffffffffu;

    // W_hh rows for this lane's 4 gates (i,f,g,o of unit l)
    float wi[HID], wf[HID], wg[HID], wo[HID];
#pragma unroll
    for (int k = 0; k < HID; k++) {
        wi[k] = Whh[(l)      * HID + k];
        wf[k] = Whh[(l + 16) * HID + k];
        wg[k] = Whh[(l + 32) * HID + k];
        wo[k] = Whh[(l + 48) * HID + k];
    }
    const float bi = b_ih[l]      + b_hh[l];
    const float bf = b_ih[l + 16] + b_hh[l + 16];
    const float bg = b_ih[l + 32] + b_hh[l + 32];
    const float bo = b_ih[l + 48] + b_hh[l + 48];

    float h = 0.0f, c = 0.0f;
    const float* xp = d_xg + (size_t)b * NG + l;

    // prefetch ring depth 4: per slot the 4 gate pre-activations
    float xi[4], xf[4], xg_[4], xo[4];
#pragma unroll
    for (int p = 0; p < 4; p++) {
        const float* q = xp + (size_t)p * STRIDE_T;
        xi[p] = q[0]; xf[p] = q[16]; xg_[p] = q[32]; xo[p] = q[48];
    }

#define STEP(S, PIDX)                                                   \
    {                                                                   \
        float gi = xi[S] + bi;                                          \
        float gf = xf[S] + bf;                                          \
        float gg = xg_[S] + bg;                                         \
        float go = xo[S] + bo;                                          \
        {                                                               \
            const float* q = xp + (size_t)(PIDX) * STRIDE_T;            \
            xi[S] = q[0]; xf[S] = q[16]; xg_[S] = q[32]; xo[S] = q[48]; \
        }                                                               \
        float hk[HID];                                                  \
        _Pragma("unroll")                                               \
        for (int k = 0; k < HID; k++)                                   \
            hk[k] = __shfl_sync(FULL, h, k, 16);                        \
        float ai = gi, aj = 0.0f, af = gf, ag2 = 0.0f;                  \
        float am = gg, an = 0.0f, ao = go, ap = 0.0f;                   \
        _Pragma("unroll")                                               \
        for (int k = 0; k < 8; k++) {                                   \
            ai  = fmaf(hk[k],     wi[k],     ai);                       \
            aj  = fmaf(hk[k + 8], wi[k + 8], aj);                       \
            af  = fmaf(hk[k],     wf[k],     af);                       \
            ag2 = fmaf(hk[k + 8], wf[k + 8], ag2);                      \
            am  = fmaf(hk[k],     wg[k],     am);                       \
            an  = fmaf(hk[k + 8], wg[k + 8], an);                       \
            ao  = fmaf(hk[k],     wo[k],     ao);                       \
            ap  = fmaf(hk[k + 8], wo[k + 8], ap);                       \
        }                                                               \
        gi = ai + aj;  gf = af + ag2;  gg = am + an;  go = ao + ap;     \
        float i_s = sigt(gi);                                           \
        float f_s = sigt(gf);                                           \
        float g_t = tanhapx(gg);                                        \
        float o_s = sigt(go);                                           \
        c = fmaf(f_s, c, i_s * g_t);                                    \
        h = o_s * tanhapx(c);                                           \
    }

    for (int t = 0; t < T_STEPS; t += 4) {
        const int p = t + 4;
        STEP(0, p + 0)
        STEP(1, p + 1)
        STEP(2, p + 2)
        STEP(3, p + 3)
    }
#undef STEP

    // ---- fused MLP head (per half-warp) ----
    float hk[HID];
#pragma unroll
    for (int k = 0; k < HID; k++) hk[k] = __shfl_sync(FULL, h, k, 16);

    float sacc = 0.0f;
#pragma unroll
    for (int q = 0; q < 4; q++) {
        int row = l + 16 * q;
        float z = b1[row];
        const float* Wr = W1 + (size_t)row * HID;
#pragma unroll
        for (int k = 0; k < HID; k++) z = fmaf(hk[k], Wr[k], z);
        z = fmaxf(z, 0.0f);
        sacc = fmaf(z, W2[row], sacc);
    }
#pragma unroll
    for (int off = 8; off > 0; off >>= 1)
        sacc += __shfl_xor_sync(FULL, sacc, off, 16);
    if (l == 0) out[b] = 4.0f * sigx(sacc + b2[0]);
}

// ---------------- launch ----------------
extern "C" void kernel_launch(void* const* d_in, const int* in_sizes, int n_in,
                              void* d_out, int out_size) {
    const float* x    = (const float*)d_in[0];
    const float* W_ih = (const float*)d_in[1];
    const float* W_hh = (const float*)d_in[2];
    const float* b_ih = (const float*)d_in[3];
    const float* b_hh = (const float*)d_in[4];
    const float* W1   = (const float*)d_in[5];
    const float* b1   = (const float*)d_in[6];
    const float* W2   = (const float*)d_in[7];
    const float* b2   = (const float*)d_in[8];
    float* out = (float*)d_out;

    cudaFuncSetAttribute(gemm_kernel, cudaFuncAttributeMaxDynamicSharedMemorySize, SMEM_BYTES);
    gemm_kernel<<<GRID_G, 256, SMEM_BYTES>>>(x, W_ih);
    scan_kernel<<<128, 64>>>(W_hh, b_ih, b_hh, W1, b1, W2, b2, out);
}

// round 10
// speedup vs baseline: 1.0513x; 1.0513x over previous
#include <cuda_runtime.h>
#include <cuda_bf16.h>
#include <cstdint>

#define T_STEPS 512
#define BATCH   512
#define INSZ    300
#define HID     16
#define NG      64
#define NROWS   (T_STEPS*BATCH)     // 262144
#define TILE_M  256
#define NTILES  (NROWS/TILE_M)      // 1024
#define GRID_G  148
#define STRIDE_T (BATCH*NG)
#define ASTRIDE 72                  // fp32 row stride in A smem (conflict-free for bf16 frags)

#define A_ELEMS (TILE_M*ASTRIDE)    // 18432 floats per buffer
#define B_WORDS (19*64*8)           // 9728 uint32 (bf16x2 pairs)
#define SMEM_BYTES (2*A_ELEMS*4 + B_WORDS*4)   // 186368

__device__ float d_xg[(size_t)(NROWS + 4 * BATCH) * NG];

// ---------------- asm helpers ----------------
__device__ __forceinline__ uint32_t smem_u32(const void* p) {
    uint32_t a;
    asm("{ .reg .u64 t; cvta.to.shared.u64 t, %1; cvt.u32.u64 %0, t; }" : "=r"(a) : "l"(p));
    return a;
}
__device__ __forceinline__ void cp16(uint32_t sa, const float* g) {
    asm volatile("cp.async.cg.shared.global [%0], [%1], 16;" :: "r"(sa), "l"(g) : "memory");
}
#define CP_COMMIT() asm volatile("cp.async.commit_group;" ::: "memory")
#define CP_WAIT1()  asm volatile("cp.async.wait_group 1;" ::: "memory")

__device__ __forceinline__ void mma16816(float* d, uint32_t a0, uint32_t a1, uint32_t a2,
                                         uint32_t a3, uint32_t b0, uint32_t b1) {
    asm volatile(
        "mma.sync.aligned.m16n8k16.row.col.f32.bf16.bf16.f32 "
        "{%0,%1,%2,%3}, {%4,%5,%6,%7}, {%8,%9}, {%0,%1,%2,%3};"
        : "+f"(d[0]), "+f"(d[1]), "+f"(d[2]), "+f"(d[3])
        : "r"(a0), "r"(a1), "r"(a2), "r"(a3), "r"(b0), "r"(b1));
}
__device__ __forceinline__ uint32_t packbf(float lo, float hi) {
    __nv_bfloat162 p = __floats2bfloat162_rn(lo, hi);
    return *reinterpret_cast<uint32_t*>(&p);
}

// copy one 64-col K-chunk of a 256-row tile (256 threads)
__device__ __forceinline__ void cp_chunk(const float* __restrict__ x, uint32_t abase,
                                         int tile, int ch) {
    const int tid = threadIdx.x;
    const int j  = tid & 15;
    const int rr = tid >> 4;
    const int c0 = ch * 64;
    const int jmax = (ch == 4) ? 11 : 16;
#pragma unroll
    for (int p = 0; p < 16; p++) {
        int r = p * 16 + rr;
        uint32_t soff = abase + ((uint32_t)(r * ASTRIDE) + 4u * (uint32_t)j) * 4u;
        if (j < jmax) {
            cp16(soff, x + (size_t)(tile * TILE_M + r) * INSZ + c0 + 4 * j);
        } else if (ch == 4 && j == 11) {
            asm volatile("st.shared.v4.u32 [%0], {%1,%1,%1,%1};" :: "r"(soff), "r"(0u) : "memory");
        }
    }
    CP_COMMIT();
}

// ---------------- GEMM: d_xg = x @ W_ih^T  (bf16 mma.sync m16n8k16, persistent) ----------------
__global__ void __launch_bounds__(256, 1)
gemm_kernel(const float* __restrict__ x, const float* __restrict__ W) {
    extern __shared__ float sm[];
    float* sA0 = sm;
    float* sA1 = sm + A_ELEMS;
    uint32_t* sB = reinterpret_cast<uint32_t*>(sm + 2 * A_ELEMS);
    const uint32_t sbase = smem_u32(sm);
    const uint32_t aB[2] = { sbase, sbase + A_ELEMS * 4u };
    float* sAp[2] = { sA0, sA1 };

    const int tid  = threadIdx.x;
    const int w    = tid >> 5;
    const int lane = tid & 31;
    const int g    = lane >> 2;
    const int tg   = lane & 3;

    cp_chunk(x, aB[0], blockIdx.x, 0);

    // B fill (once): W[n][k] fp32 -> bf16x2 fragment-pair layout
    for (int i = tid; i < 19 * 64 * 4; i += 256) {
        int s = i >> 8;
        int n = (i >> 2) & 63;
        int t = i & 3;
        int k0 = 16 * s + 2 * t;
        const float* Wn = W + (size_t)n * INSZ;
        float v0 = (k0     < INSZ) ? Wn[k0]     : 0.0f;
        float v1 = (k0 + 1 < INSZ) ? Wn[k0 + 1] : 0.0f;
        float v2 = (k0 + 8 < INSZ) ? Wn[k0 + 8] : 0.0f;
        float v3 = (k0 + 9 < INSZ) ? Wn[k0 + 9] : 0.0f;
        int base = ((s * 64 + n) * 4 + t) * 2;
        sB[base]     = packbf(v0, v1);
        sB[base + 1] = packbf(v2, v3);
    }
    __syncthreads();

    int buf = 0;
    for (int tile = blockIdx.x; tile < NTILES; tile += GRID_G) {
        float acc[2][8][4];
#pragma unroll
        for (int i = 0; i < 2; i++)
#pragma unroll
            for (int j = 0; j < 8; j++)
#pragma unroll
                for (int r = 0; r < 4; r++) acc[i][j][r] = 0.0f;

        for (int ch = 0; ch < 5; ch++) {
            int ntile = tile, nch = ch + 1;
            if (nch == 5) { ntile = tile + GRID_G; nch = 0; }
            if (ntile < NTILES) cp_chunk(x, aB[buf ^ 1], ntile, nch);
            else CP_COMMIT();
            CP_WAIT1();
            __syncthreads();

            const float* A = sAp[buf];
            const int nsl = (ch == 4) ? 3 : 4;
            for (int sl = 0; sl < nsl; sl++) {
                const int s = ch * 4 + sl;
                uint2 bb[8];
                const uint2* Bf = reinterpret_cast<const uint2*>(sB)
                                + ((s * 64 + g) * 4 + tg);
#pragma unroll
                for (int j = 0; j < 8; j++) bb[j] = Bf[j * 32];
#pragma unroll
                for (int i = 0; i < 2; i++) {
                    int r0 = w * 32 + i * 16 + g;
                    const float* Ab = A + r0 * ASTRIDE + sl * 16 + 2 * tg;
                    float2 f0 = *reinterpret_cast<const float2*>(Ab);
                    float2 f1 = *reinterpret_cast<const float2*>(Ab + 8 * ASTRIDE);
                    float2 f2 = *reinterpret_cast<const float2*>(Ab + 8);
                    float2 f3 = *reinterpret_cast<const float2*>(Ab + 8 * ASTRIDE + 8);
                    uint32_t a0 = packbf(f0.x, f0.y);
                    uint32_t a1 = packbf(f1.x, f1.y);
                    uint32_t a2 = packbf(f2.x, f2.y);
                    uint32_t a3 = packbf(f3.x, f3.y);
#pragma unroll
                    for (int j = 0; j < 8; j++)
                        mma16816(acc[i][j], a0, a1, a2, a3, bb[j].x, bb[j].y);
                }
            }
            __syncthreads();
            buf ^= 1;
        }

#pragma unroll
        for (int i = 0; i < 2; i++) {
            int r0 = tile * TILE_M + w * 32 + i * 16 + g;
#pragma unroll
            for (int j = 0; j < 8; j++) {
                int col = j * 8 + tg * 2;
                *reinterpret_cast<float2*>(&d_xg[(size_t)r0 * NG + col]) =
                    make_float2(acc[i][j][0], acc[i][j][1]);
                *reinterpret_cast<float2*>(&d_xg[(size_t)(r0 + 8) * NG + col]) =
                    make_float2(acc[i][j][2], acc[i][j][3]);
            }
        }
    }
}

// ---------------- scan: 1 elem/warp, smem h-broadcast, activate-then-exchange ----------------
__device__ __forceinline__ float tanhapx(float x) {
    float y;
    asm("tanh.approx.f32 %0, %1;" : "=f"(y) : "f"(x));
    return y;
}
__device__ __forceinline__ float sigx(float x) {
    float e = __expf(-x);
    return __fdividef(1.0f, 1.0f + e);
}

__global__ void __launch_bounds__(128, 1)
scan_kernel(const float* __restrict__ Whh,
            const float* __restrict__ b_ih, const float* __restrict__ b_hh,
            const float* __restrict__ W1, const float* __restrict__ b1,
            const float* __restrict__ W2, const float* __restrict__ b2,
            float* __restrict__ out) {
    __shared__ float sh[4][32];          // per-warp h slot (128B apart)
    const int warp = threadIdx.x >> 5;
    const int lane = threadIdx.x & 31;
    const int b = blockIdx.x * 4 + warp;
    const unsigned FULL = 0xffffffffu;
    const bool lo16 = (lane < 16);
    float* hs = sh[warp];

    // lane computes gates 'lane' (i/f block) and 'lane+32' (g/o block)
    float w1r[HID], w2r[HID];
#pragma unroll
    for (int k = 0; k < HID; k++) {
        w1r[k] = Whh[lane * HID + k];
        w2r[k] = Whh[(lane + 32) * HID + k];
    }
    const float biasA = b_ih[lane] + b_hh[lane];
    const float biasB = b_ih[lane + 32] + b_hh[lane + 32];

    float h = 0.0f, c = 0.0f;
    if (lo16) hs[lane] = 0.0f;
    __syncwarp();

    const float* xpA = d_xg + (size_t)b * NG + lane;
    const float* xpB = xpA + 32;

    float xa0 = xpA[0 * STRIDE_T], xb0 = xpB[0 * STRIDE_T];
    float xa1 = xpA[1 * STRIDE_T], xb1 = xpB[1 * STRIDE_T];
    float xa2 = xpA[2 * STRIDE_T], xb2 = xpB[2 * STRIDE_T];
    float xa3 = xpA[3 * STRIDE_T], xb3 = xpB[3 * STRIDE_T];
    const float* pA = xpA + 4 * STRIDE_T;   // prefetch cursors
    const float* pB = xpB + 4 * STRIDE_T;

#define STEP(XA, XB, QOFF)                                              \
    {                                                                   \
        float g1 = XA + biasA;                                          \
        float g2 = XB + biasB;                                          \
        XA = pA[(QOFF) * STRIDE_T];                                     \
        XB = pB[(QOFF) * STRIDE_T];                                     \
        float4 h0 = *reinterpret_cast<const float4*>(hs);               \
        float4 h1 = *reinterpret_cast<const float4*>(hs + 4);           \
        float4 h2 = *reinterpret_cast<const float4*>(hs + 8);           \
        float4 h3 = *reinterpret_cast<const float4*>(hs + 12);          \
        float s0 = g1, s1 = 0.0f, s2 = 0.0f, s3 = 0.0f;                 \
        float r0 = g2, r1 = 0.0f, r2 = 0.0f, r3 = 0.0f;                 \
        s0 = fmaf(h0.x, w1r[0],  s0);  r0 = fmaf(h0.x, w2r[0],  r0);    \
        s1 = fmaf(h0.y, w1r[1],  s1);  r1 = fmaf(h0.y, w2r[1],  r1);    \
        s2 = fmaf(h0.z, w1r[2],  s2);  r2 = fmaf(h0.z, w2r[2],  r2);    \
        s3 = fmaf(h0.w, w1r[3],  s3);  r3 = fmaf(h0.w, w2r[3],  r3);    \
        s0 = fmaf(h1.x, w1r[4],  s0);  r0 = fmaf(h1.x, w2r[4],  r0);    \
        s1 = fmaf(h1.y, w1r[5],  s1);  r1 = fmaf(h1.y, w2r[5],  r1);    \
        s2 = fmaf(h1.z, w1r[6],  s2);  r2 = fmaf(h1.z, w2r[6],  r2);    \
        s3 = fmaf(h1.w, w1r[7],  s3);  r3 = fmaf(h1.w, w2r[7],  r3);    \
        s0 = fmaf(h2.x, w1r[8],  s0);  r0 = fmaf(h2.x, w2r[8],  r0);    \
        s1 = fmaf(h2.y, w1r[9],  s1);  r1 = fmaf(h2.y, w2r[9],  r1);    \
        s2 = fmaf(h2.z, w1r[10], s2);  r2 = fmaf(h2.z, w2r[10], r2);    \
        s3 = fmaf(h2.w, w1r[11], s3);  r3 = fmaf(h2.w, w2r[11], r3);    \
        s0 = fmaf(h3.x, w1r[12], s0);  r0 = fmaf(h3.x, w2r[12], r0);    \
        s1 = fmaf(h3.y, w1r[13], s1);  r1 = fmaf(h3.y, w2r[13], r1);    \
        s2 = fmaf(h3.z, w1r[14], s2);  r2 = fmaf(h3.z, w2r[14], r2);    \
        s3 = fmaf(h3.w, w1r[15], s3);  r3 = fmaf(h3.w, w2r[15], r3);    \
        g1 = (s0 + s1) + (s2 + s3);                                     \
        g2 = (r0 + r1) + (r2 + r3);                                     \
        /* act1 = sigmoid(g1) for all lanes (i for lo16, f for hi16) */ \
        float act1 = fmaf(tanhapx(0.5f * g1), 0.5f, 0.5f);              \
        /* act2: tanh(g2) on lo16 (g), sigmoid(g2) on hi16 (o) */       \
        float t2 = tanhapx(lo16 ? g2 : 0.5f * g2);                      \
        float act2 = lo16 ? t2 : fmaf(t2, 0.5f, 0.5f);                  \
        float f_s = __shfl_sync(FULL, act1, lane + 16);                 \
        float o_s = __shfl_sync(FULL, act2, lane + 16);                 \
        c = fmaf(f_s, c, act1 * act2);                                  \
        h = o_s * tanhapx(c);                                           \
        if (lo16) hs[lane] = h;                                         \
        __syncwarp();                                                   \
    }

    for (int t = 0; t < T_STEPS; t += 4) {
        STEP(xa0, xb0, 0)
        STEP(xa1, xb1, 1)
        STEP(xa2, xb2, 2)
        STEP(xa3, xb3, 3)
        pA += 4 * STRIDE_T;
        pB += 4 * STRIDE_T;
    }
#undef STEP

    // ---- fused MLP head ----
    float hk[HID];
#pragma unroll
    for (int k = 0; k < HID; k++) hk[k] = hs[k];

    float wa[HID], wb[HID];
#pragma unroll
    for (int k = 0; k < HID; k++) {
        wa[k] = W1[lane * HID + k];
        wb[k] = W1[(lane + 32) * HID + k];
    }
    float za = b1[lane], zb = b1[lane + 32];
#pragma unroll
    for (int k = 0; k < HID; k++) {
        za = fmaf(hk[k], wa[k], za);
        zb = fmaf(hk[k], wb[k], zb);
    }
    za = fmaxf(za, 0.0f);
    zb = fmaxf(zb, 0.0f);
    float sacc = za * W2[lane] + zb * W2[lane + 32];
#pragma unroll
    for (int off = 16; off > 0; off >>= 1)
        sacc += __shfl_xor_sync(FULL, sacc, off);
    if (lane == 0) out[b] = 4.0f * sigx(sacc + b2[0]);
}

// ---------------- launch ----------------
extern "C" void kernel_launch(void* const* d_in, const int* in_sizes, int n_in,
                              void* d_out, int out_size) {
    const float* x    = (const float*)d_in[0];
    const float* W_ih = (const float*)d_in[1];
    const float* W_hh = (const float*)d_in[2];
    const float* b_ih = (const float*)d_in[3];
    const float* b_hh = (const float*)d_in[4];
    const float* W1   = (const float*)d_in[5];
    const float* b1   = (const float*)d_in[6];
    const float* W2   = (const float*)d_in[7];
    const float* b2   = (const float*)d_in[8];
    float* out = (float*)d_out;

    cudaFuncSetAttribute(gemm_kernel, cudaFuncAttributeMaxDynamicSharedMemorySize, SMEM_BYTES);
    gemm_kernel<<<GRID_G, 256, SMEM_BYTES>>>(x, W_ih);
    scan_kernel<<<128, 128>>>(W_hh, b_ih, b_hh, W1, b1, W2, b2, out);
}